// round 14
// baseline (speedup 1.0000x reference)
#include <cuda_runtime.h>

#define N_NODES 50000
#define N_EDGES 800000

#if defined(__CUDA_ARCH__) && (__CUDA_ARCH__ >= 900)
#define GRID_DEP_SYNC() cudaGridDependencySynchronize()
#else
#define GRID_DEP_SYNC()
#endif

// ---------------- scratch ----------------
__device__ __align__(16) float g_agg48[N_NODES * 48];  // [n]: x-sum(16), c-sum(32 sample-major)
__device__ float g_s1[2][64];
__device__ float g_s2[2][64];

// ---------------- packed f32x2 helpers ----------------
typedef unsigned long long u64;
__device__ __forceinline__ u64 dup2(float v) {
    u64 r; asm("mov.b64 %0, {%1,%1};" : "=l"(r) : "f"(v)); return r;
}
__device__ __forceinline__ u64 pack2(float lo, float hi) {
    u64 r; asm("mov.b64 %0, {%1,%2};" : "=l"(r) : "f"(lo), "f"(hi)); return r;
}
__device__ __forceinline__ void fma2(u64 &d, u64 a, u64 b) {
    asm("fma.rn.f32x2 %0, %1, %2, %3;" : "=l"(d) : "l"(a), "l"(b), "l"(d));
}
__device__ __forceinline__ u64 add2(u64 a, u64 b) {
    u64 r; asm("add.rn.f32x2 %0, %1, %2;" : "=l"(r) : "l"(a), "l"(b)); return r;
}
__device__ __forceinline__ void unpack2(u64 v, float &lo, float &hi) {
    asm("mov.b64 {%0,%1}, %2;" : "=f"(lo), "=f"(hi) : "l"(v));
}
__device__ __forceinline__ void lds_v2u64(u64 &a, u64 &b, const void* p) {
    unsigned sa = (unsigned)__cvta_generic_to_shared(p);
    asm("ld.shared.v2.u64 {%0, %1}, [%2];" : "=l"(a), "=l"(b) : "r"(sa));
}
__device__ __forceinline__ void red4(float4* p, float4 v) {
    asm volatile("red.global.add.v4.f32 [%0], {%1,%2,%3,%4};"
                 :: "l"(p), "f"(v.x), "f"(v.y), "f"(v.z), "f"(v.w) : "memory");
}

// ================= K0: zero everything ==========================================
__global__ void k_zero() {
    int t = blockIdx.x * 256 + threadIdx.x;
    if (t < 600000) ((float4*)g_agg48)[t] = make_float4(0.f, 0.f, 0.f, 0.f);
    if (t < 128) { ((float*)g_s1)[t] = 0.f; ((float*)g_s2)[t] = 0.f; }
}

// ================= K1: edge scatter (4 threads/edge, 3 red.v4 each) ==============
// PDL: input loads before gridsync; red4 (touches zeroed g_agg48) after.
__global__ void __launch_bounds__(256) k_scatter(const int* __restrict__ ei,
                                                 const float* __restrict__ x,
                                                 const float* __restrict__ c) {
    unsigned tid = blockIdx.x * 256u + threadIdx.x;
    unsigned e = tid >> 2;
    if (e >= N_EDGES) { GRID_DEP_SYNC(); return; }
    unsigned q = tid & 3;
    int src = __ldg(ei + e);
    int dst = __ldg(ei + N_EDGES + e);
    const float4* x4 = reinterpret_cast<const float4*>(x);
    const float4* c4 = reinterpret_cast<const float4*>(c);
    float4 vx = __ldg(&x4[src * 4 + q]);
    float4 v0 = __ldg(&c4[src * 8 + q]);
    float4 v1 = __ldg(&c4[src * 8 + 4 + q]);
    GRID_DEP_SYNC();
    float4* d = reinterpret_cast<float4*>(g_agg48) + dst * 12;
    red4(d + q, vx);
    red4(d + 4 + q, v0);
    red4(d + 8 + q, v1);
}

// ================= K2: BN moment stats (layer-1 for both paths, factored) ========
__global__ void __launch_bounds__(256) k_stats(const float* __restrict__ x,
                                               const float* __restrict__ c,
                                               const float* __restrict__ W1s,
                                               const float* __restrict__ b1s,
                                               const float* __restrict__ W1a,
                                               const float* __restrict__ b1a,
                                               const float* __restrict__ eps_s_p,
                                               const float* __restrict__ eps_a_p) {
    __shared__ float4 w1qs[24][16], w1qa[24][16];
    __shared__ float msx[8][2][16], msc[8][2][4][8];
    __shared__ float max_[8][2][16], mac[8][2][8];
    __shared__ float red[8][16][16];
    int tid = threadIdx.x;
    for (int i = tid; i < 24 * 16; i += 256) {
        int j = i >> 4, l = i & 15;
        w1qs[j][l] = *reinterpret_cast<const float4*>(&W1s[j * 64 + 4 * l]);
        w1qa[j][l] = *reinterpret_cast<const float4*>(&W1a[j * 64 + 4 * l]);
    }
    float es = 1.f + __ldg(eps_s_p);
    float ea = 1.f + __ldg(eps_a_p);
    int w = tid >> 5, lane = tid & 31, l16 = lane & 15, nd = lane >> 4;
    float4 bs4 = __ldg(reinterpret_cast<const float4*>(b1s) + l16);
    float4 ba4 = __ldg(reinterpret_cast<const float4*>(b1a) + l16);
    u64 bs0 = pack2(bs4.x, bs4.y), bs1 = pack2(bs4.z, bs4.w);
    u64 ba0 = pack2(ba4.x, ba4.y), ba1 = pack2(ba4.z, ba4.w);
    GRID_DEP_SYNC();   // g_agg48 reads below depend on k_scatter
    __syncthreads();
    float ss[4] = {0,0,0,0}, sq[4] = {0,0,0,0}, as_[4] = {0,0,0,0}, aq[4] = {0,0,0,0};
    for (int p = blockIdx.x * 8 + w; p < 25000; p += gridDim.x * 8) {
        int nA = 2 * p;
        __syncwarp();
#pragma unroll
        for (int it = 0; it < 4; it++) {
            int idx = lane + 32 * it;
            int node = idx >> 6, r = idx & 63, n = nA + node;
            if (r < 16) msx[w][node][r] = es * x[n * 16 + r] + g_agg48[n * 48 + r];
            else if (r < 48) {
                int s = (r - 16) >> 3, j = (r - 16) & 7;
                msc[w][node][s][j] = es * c[n * 32 + s * 8 + j] + g_agg48[n * 48 + 16 + s * 8 + j];
            } else {
                int j = r - 48;
                max_[w][node][j] = ea * x[n * 16 + j] + g_agg48[n * 48 + j];
            }
        }
        __syncwarp();
        if (lane < 16) {
            int node = lane >> 3, j = lane & 7, n = nA + node;
            float csum = c[n*32 + j] + c[n*32 + 8 + j] + c[n*32 + 16 + j] + c[n*32 + 24 + j];
            float msum = msc[w][node][0][j] + msc[w][node][1][j]
                       + msc[w][node][2][j] + msc[w][node][3][j];
            mac[w][node][j] = 0.25f * (msum + (ea - es) * csum);
        }
        __syncwarp();
        u64 zc0 = bs0, zc1 = bs1, za0 = ba0, za1 = ba1;
#pragma unroll
        for (int j = 0; j < 16; j++) {
            u64 w0, w1; lds_v2u64(w0, w1, &w1qs[j][l16]);
            u64 h = dup2(msx[w][nd][j]);
            fma2(zc0, w0, h); fma2(zc1, w1, h);
            u64 a0, a1; lds_v2u64(a0, a1, &w1qa[j][l16]);
            u64 ha = dup2(max_[w][nd][j]);
            fma2(za0, a0, ha); fma2(za1, a1, ha);
        }
        u64 zs0[4], zs1[4];
#pragma unroll
        for (int s = 0; s < 4; s++) { zs0[s] = zc0; zs1[s] = zc1; }
#pragma unroll
        for (int j = 0; j < 8; j++) {
            u64 w0, w1; lds_v2u64(w0, w1, &w1qs[16 + j][l16]);
#pragma unroll
            for (int s = 0; s < 4; s++) {
                u64 h = dup2(msc[w][nd][s][j]);
                fma2(zs0[s], w0, h); fma2(zs1[s], w1, h);
            }
            u64 a0, a1; lds_v2u64(a0, a1, &w1qa[16 + j][l16]);
            u64 ha = dup2(mac[w][nd][j]);
            fma2(za0, a0, ha); fma2(za1, a1, ha);
        }
#pragma unroll
        for (int s = 0; s < 4; s++) {
            float z0, z1, z2, z3;
            unpack2(zs0[s], z0, z1); unpack2(zs1[s], z2, z3);
            ss[0] += z0; ss[1] += z1; ss[2] += z2; ss[3] += z3;
            sq[0] += z0*z0; sq[1] += z1*z1; sq[2] += z2*z2; sq[3] += z3*z3;
        }
        {
            float z0, z1, z2, z3;
            unpack2(za0, z0, z1); unpack2(za1, z2, z3);
            as_[0] += z0; as_[1] += z1; as_[2] += z2; as_[3] += z3;
            aq[0] += z0*z0; aq[1] += z1*z1; aq[2] += z2*z2; aq[3] += z3*z3;
        }
    }
#pragma unroll
    for (int i = 0; i < 4; i++) {
        ss[i]  += __shfl_xor_sync(0xffffffffu, ss[i], 16);
        sq[i]  += __shfl_xor_sync(0xffffffffu, sq[i], 16);
        as_[i] += __shfl_xor_sync(0xffffffffu, as_[i], 16);
        aq[i]  += __shfl_xor_sync(0xffffffffu, aq[i], 16);
    }
    if (lane < 16) {
#pragma unroll
        for (int i = 0; i < 4; i++) {
            red[w][l16][i]      = ss[i];
            red[w][l16][4 + i]  = sq[i];
            red[w][l16][8 + i]  = as_[i];
            red[w][l16][12 + i] = aq[i];
        }
    }
    __syncthreads();
    {
        int l = tid >> 4, v = tid & 15;
        float acc = 0.f;
#pragma unroll
        for (int ww = 0; ww < 8; ww++) acc += red[ww][l][v];
        int col = 4 * l + (v & 3);
        if (v < 4)       atomicAdd(&g_s1[0][col], acc);
        else if (v < 8)  atomicAdd(&g_s2[0][col], acc);
        else if (v < 12) atomicAdd(&g_s1[1][col], acc);
        else             atomicAdd(&g_s2[1][col], acc);
    }
}

// ================= K3: fused both-path MLP, 4 nodes/warp + DSS -> out ============
// cons rows: 0/1 b1s, 2/3 b1a, 4/5 b2s, 6/7 b2a,
//            8/9 alpha_s, 10/11 beta_s, 12/13 alpha_a, 14/15 beta_a  (lo/hi pairs)
__global__ void __launch_bounds__(256, 2) k_main(const float* __restrict__ x,
                                              const float* __restrict__ c,
                                              const float* __restrict__ W1s,
                                              const float* __restrict__ b1s,
                                              const float* __restrict__ g1s,
                                              const float* __restrict__ be1s,
                                              const float* __restrict__ W2s,
                                              const float* __restrict__ b2s,
                                              const float* __restrict__ W1a,
                                              const float* __restrict__ b1a,
                                              const float* __restrict__ g1a,
                                              const float* __restrict__ be1a,
                                              const float* __restrict__ W2a,
                                              const float* __restrict__ b2a,
                                              const float* __restrict__ eps_s_p,
                                              const float* __restrict__ eps_a_p,
                                              float* __restrict__ out) {
    __shared__ float4 w1qs[24][16], w1qa[24][16];
    __shared__ float4 w2qs[64][16], w2qa[64][16];
    __shared__ u64 cons[16][16];
    __shared__ float msx[8][4][16], msc[8][4][4][8];
    __shared__ float max_[8][4][16], mac[8][4][8];
    __shared__ __align__(16) float hs[8][4][5][64];
    int tid = threadIdx.x;
    // ---- preamble independent of predecessors: weight tables + bias rows ----
    for (int i = tid; i < 24 * 16; i += 256) {
        int j = i >> 4, l = i & 15;
        w1qs[j][l] = *reinterpret_cast<const float4*>(&W1s[j * 64 + 4 * l]);
        w1qa[j][l] = *reinterpret_cast<const float4*>(&W1a[j * 64 + 4 * l]);
    }
    for (int i = tid; i < 64 * 16; i += 256) {
        int k = i >> 4, l = i & 15;
        w2qs[k][l] = *reinterpret_cast<const float4*>(&W2s[k * 64 + 4 * l]);
        w2qa[k][l] = *reinterpret_cast<const float4*>(&W2a[k * 64 + 4 * l]);
    }
    if (tid < 16) {
        float4 v;
        v = __ldg(reinterpret_cast<const float4*>(b1s) + tid);
        cons[0][tid] = pack2(v.x, v.y); cons[1][tid] = pack2(v.z, v.w);
        v = __ldg(reinterpret_cast<const float4*>(b1a) + tid);
        cons[2][tid] = pack2(v.x, v.y); cons[3][tid] = pack2(v.z, v.w);
        v = __ldg(reinterpret_cast<const float4*>(b2s) + tid);
        cons[4][tid] = pack2(v.x, v.y); cons[5][tid] = pack2(v.z, v.w);
        v = __ldg(reinterpret_cast<const float4*>(b2a) + tid);
        cons[6][tid] = pack2(v.x, v.y); cons[7][tid] = pack2(v.z, v.w);
    }
    float es = 1.f + __ldg(eps_s_p);
    float ea = 1.f + __ldg(eps_a_p);
    GRID_DEP_SYNC();   // g_s1/g_s2 (BN fold) and g_agg48 depend on k_stats/k_scatter
    if (tid < 16) {
        {
            float4 s1v = *reinterpret_cast<const float4*>(&g_s1[0][4 * tid]);
            float4 s2v = *reinterpret_cast<const float4*>(&g_s2[0][4 * tid]);
            float4 g1v = __ldg(reinterpret_cast<const float4*>(g1s) + tid);
            float4 bev = __ldg(reinterpret_cast<const float4*>(be1s) + tid);
            const float invR = 1.f / 200000.f;
            float m0 = s1v.x*invR, m1 = s1v.y*invR, m2 = s1v.z*invR, m3 = s1v.w*invR;
            float a0 = g1v.x * rsqrtf(s2v.x*invR - m0*m0 + 1e-5f);
            float a1 = g1v.y * rsqrtf(s2v.y*invR - m1*m1 + 1e-5f);
            float a2 = g1v.z * rsqrtf(s2v.z*invR - m2*m2 + 1e-5f);
            float a3 = g1v.w * rsqrtf(s2v.w*invR - m3*m3 + 1e-5f);
            cons[8][tid]  = pack2(a0, a1); cons[9][tid]  = pack2(a2, a3);
            cons[10][tid] = pack2(bev.x - a0*m0, bev.y - a1*m1);
            cons[11][tid] = pack2(bev.z - a2*m2, bev.w - a3*m3);
        }
        {
            float4 s1v = *reinterpret_cast<const float4*>(&g_s1[1][4 * tid]);
            float4 s2v = *reinterpret_cast<const float4*>(&g_s2[1][4 * tid]);
            float4 g1v = __ldg(reinterpret_cast<const float4*>(g1a) + tid);
            float4 bev = __ldg(reinterpret_cast<const float4*>(be1a) + tid);
            const float invR = 1.f / 50000.f;
            float m0 = s1v.x*invR, m1 = s1v.y*invR, m2 = s1v.z*invR, m3 = s1v.w*invR;
            float a0 = g1v.x * rsqrtf(s2v.x*invR - m0*m0 + 1e-5f);
            float a1 = g1v.y * rsqrtf(s2v.y*invR - m1*m1 + 1e-5f);
            float a2 = g1v.z * rsqrtf(s2v.z*invR - m2*m2 + 1e-5f);
            float a3 = g1v.w * rsqrtf(s2v.w*invR - m3*m3 + 1e-5f);
            cons[12][tid] = pack2(a0, a1); cons[13][tid] = pack2(a2, a3);
            cons[14][tid] = pack2(bev.x - a0*m0, bev.y - a1*m1);
            cons[15][tid] = pack2(bev.z - a2*m2, bev.w - a3*m3);
        }
    }
    int w = tid >> 5, lane = tid & 31, l16 = lane & 15, nd = lane >> 4;
    __syncthreads();
    for (int p = blockIdx.x * 8 + w; p < 12500; p += gridDim.x * 8) {
        int nA = 4 * p;
        __syncwarp();
        // ---- build rows for 4 nodes ----
#pragma unroll
        for (int it = 0; it < 8; it++) {
            int idx = lane + 32 * it;
            int node = idx >> 6, r = idx & 63, nn = nA + node;
            if (r < 16) msx[w][node][r] = es * x[nn * 16 + r] + g_agg48[nn * 48 + r];
            else if (r < 48) {
                int s = (r - 16) >> 3, j = (r - 16) & 7;
                msc[w][node][s][j] = es * c[nn * 32 + s * 8 + j] + g_agg48[nn * 48 + 16 + s * 8 + j];
            } else {
                int j = r - 48;
                max_[w][node][j] = ea * x[nn * 16 + j] + g_agg48[nn * 48 + j];
            }
        }
        __syncwarp();
        {
            int node = lane >> 3, j = lane & 7, nn = nA + node;
            float csum = c[nn*32 + j] + c[nn*32 + 8 + j] + c[nn*32 + 16 + j] + c[nn*32 + 24 + j];
            float msum = msc[w][node][0][j] + msc[w][node][1][j]
                       + msc[w][node][2][j] + msc[w][node][3][j];
            mac[w][node][j] = 0.25f * (msum + (ea - es) * csum);
        }
        __syncwarp();
        // ---- layer 1, half-warp nd handles local nodes 2nd, 2nd+1 ----
        u64 zc[2][2], za[2][2];
#pragma unroll
        for (int i = 0; i < 2; i++) {
            zc[i][0] = cons[0][l16]; zc[i][1] = cons[1][l16];
            za[i][0] = cons[2][l16]; za[i][1] = cons[3][l16];
        }
#pragma unroll
        for (int j = 0; j < 16; j++) {
            u64 w0, w1; lds_v2u64(w0, w1, &w1qs[j][l16]);
            u64 a0, a1; lds_v2u64(a0, a1, &w1qa[j][l16]);
#pragma unroll
            for (int i = 0; i < 2; i++) {
                u64 h = dup2(msx[w][2 * nd + i][j]);
                fma2(zc[i][0], w0, h); fma2(zc[i][1], w1, h);
                u64 ha = dup2(max_[w][2 * nd + i][j]);
                fma2(za[i][0], a0, ha); fma2(za[i][1], a1, ha);
            }
        }
        u64 zs[2][4][2];
#pragma unroll
        for (int i = 0; i < 2; i++)
#pragma unroll
            for (int s = 0; s < 4; s++) { zs[i][s][0] = zc[i][0]; zs[i][s][1] = zc[i][1]; }
#pragma unroll
        for (int j = 0; j < 8; j++) {
            u64 w0, w1; lds_v2u64(w0, w1, &w1qs[16 + j][l16]);
            u64 a0, a1; lds_v2u64(a0, a1, &w1qa[16 + j][l16]);
#pragma unroll
            for (int i = 0; i < 2; i++) {
#pragma unroll
                for (int s = 0; s < 4; s++) {
                    u64 h = dup2(msc[w][2 * nd + i][s][j]);
                    fma2(zs[i][s][0], w0, h); fma2(zs[i][s][1], w1, h);
                }
                u64 ha = dup2(mac[w][2 * nd + i][j]);
                fma2(za[i][0], a0, ha); fma2(za[i][1], a1, ha);
            }
        }
        // ---- BN + relu -> hs ----
#pragma unroll
        for (int i = 0; i < 2; i++) {
#pragma unroll
            for (int s = 0; s < 4; s++) {
                u64 t0 = cons[10][l16], t1 = cons[11][l16];
                fma2(t0, cons[8][l16], zs[i][s][0]); fma2(t1, cons[9][l16], zs[i][s][1]);
                float r0, r1, r2, r3;
                unpack2(t0, r0, r1); unpack2(t1, r2, r3);
                *reinterpret_cast<float4*>(&hs[w][2 * nd + i][s][4 * l16]) =
                    make_float4(fmaxf(r0, 0.f), fmaxf(r1, 0.f), fmaxf(r2, 0.f), fmaxf(r3, 0.f));
            }
            u64 t0 = cons[14][l16], t1 = cons[15][l16];
            fma2(t0, cons[12][l16], za[i][0]); fma2(t1, cons[13][l16], za[i][1]);
            float r0, r1, r2, r3;
            unpack2(t0, r0, r1); unpack2(t1, r2, r3);
            *reinterpret_cast<float4*>(&hs[w][2 * nd + i][4][4 * l16]) =
                make_float4(fmaxf(r0, 0.f), fmaxf(r1, 0.f), fmaxf(r2, 0.f), fmaxf(r3, 0.f));
        }
        __syncwarp();
        // ---- layer 2: 2 nodes x 5 rows per half-warp ----
        u64 o[2][5][2];
#pragma unroll
        for (int i = 0; i < 2; i++) {
#pragma unroll
            for (int s = 0; s < 4; s++) { o[i][s][0] = cons[4][l16]; o[i][s][1] = cons[5][l16]; }
            o[i][4][0] = cons[6][l16]; o[i][4][1] = cons[7][l16];
        }
#pragma unroll
        for (int k0 = 0; k0 < 64; k0 += 2) {
            float2 hv[2][5];
#pragma unroll
            for (int i = 0; i < 2; i++)
#pragma unroll
                for (int s = 0; s < 5; s++)
                    hv[i][s] = *reinterpret_cast<const float2*>(&hs[w][2 * nd + i][s][k0]);
#pragma unroll
            for (int kk = 0; kk < 2; kk++) {
                u64 w0, w1; lds_v2u64(w0, w1, &w2qs[k0 + kk][l16]);
                u64 a0, a1; lds_v2u64(a0, a1, &w2qa[k0 + kk][l16]);
#pragma unroll
                for (int i = 0; i < 2; i++) {
#pragma unroll
                    for (int s = 0; s < 4; s++) {
                        u64 h = dup2(kk ? hv[i][s].y : hv[i][s].x);
                        fma2(o[i][s][0], w0, h); fma2(o[i][s][1], w1, h);
                    }
                    u64 h4 = dup2(kk ? hv[i][4].y : hv[i][4].x);
                    fma2(o[i][4][0], a0, h4); fma2(o[i][4][1], a1, h4);
                }
            }
        }
        // ---- DSS combine + store ----
#pragma unroll
        for (int i = 0; i < 2; i++) {
            int n = nA + 2 * nd + i;
#pragma unroll
            for (int s = 0; s < 4; s++) {
                u64 t0 = add2(o[i][s][0], o[i][4][0]);
                u64 t1 = add2(o[i][s][1], o[i][4][1]);
                float r0, r1, r2, r3;
                unpack2(t0, r0, r1); unpack2(t1, r2, r3);
                *reinterpret_cast<float4*>(&out[n * 256 + s * 64 + 4 * l16]) =
                    make_float4(r0, r1, r2, r3);
            }
        }
    }
}

// ================= launch (PDL-chained) ==========================================
template <typename F, typename... Args>
static void launch_pdl(F func, int grid, int block, Args... args) {
    cudaLaunchConfig_t cfg = {};
    cfg.gridDim = dim3(grid, 1, 1);
    cfg.blockDim = dim3(block, 1, 1);
    cudaLaunchAttribute attr[1];
    attr[0].id = cudaLaunchAttributeProgrammaticStreamSerialization;
    attr[0].val.programmaticStreamSerializationAllowed = 1;
    cfg.attrs = attr;
    cfg.numAttrs = 1;
    cudaLaunchKernelEx(&cfg, func, args...);
}

extern "C" void kernel_launch(void* const* d_in, const int* in_sizes, int n_in,
                              void* d_out, int out_size) {
    const float* x     = (const float*)d_in[0];
    const float* c     = (const float*)d_in[1];
    const int*   ei    = (const int*)  d_in[2];
    const float* eps_s = (const float*)d_in[3];
    const float* W1s   = (const float*)d_in[4];
    const float* b1s   = (const float*)d_in[5];
    const float* g1s   = (const float*)d_in[6];
    const float* be1s  = (const float*)d_in[7];
    const float* W2s   = (const float*)d_in[8];
    const float* b2s   = (const float*)d_in[9];
    const float* eps_a = (const float*)d_in[10];
    const float* W1a   = (const float*)d_in[11];
    const float* b1a   = (const float*)d_in[12];
    const float* g1a   = (const float*)d_in[13];
    const float* be1a  = (const float*)d_in[14];
    const float* W2a   = (const float*)d_in[15];
    const float* b2a   = (const float*)d_in[16];
    float* out = (float*)d_out;

    k_zero<<<2344, 256>>>();
    launch_pdl(k_scatter, (N_EDGES * 4 + 255) / 256, 256, ei, x, c);
    launch_pdl(k_stats, 296, 256, x, c, W1s, b1s, W1a, b1a, eps_s, eps_a);
    launch_pdl(k_main, 296, 256, x, c, W1s, b1s, g1s, be1s, W2s, b2s,
               W1a, b1a, g1a, be1a, W2a, b2a, eps_s, eps_a, out);
}

// round 15
// speedup vs baseline: 1.0987x; 1.0987x over previous
#include <cuda_runtime.h>

#define N_NODES 50000
#define N_EDGES 800000

// ---------------- scratch ----------------
__device__ __align__(16) float g_agg48[N_NODES * 48];  // [n]: x-sum(16), c-sum(32 sample-major)
__device__ float g_s1[2][64];
__device__ float g_s2[2][64];
__device__ __align__(16) float g_z[N_NODES * 320];     // pre-BN z: [n][row 0-3 shared s, 4 agg][64]

// ---------------- packed f32x2 helpers ----------------
typedef unsigned long long u64;
__device__ __forceinline__ u64 dup2(float v) {
    u64 r; asm("mov.b64 %0, {%1,%1};" : "=l"(r) : "f"(v)); return r;
}
__device__ __forceinline__ u64 pack2(float lo, float hi) {
    u64 r; asm("mov.b64 %0, {%1,%2};" : "=l"(r) : "f"(lo), "f"(hi)); return r;
}
__device__ __forceinline__ void fma2(u64 &d, u64 a, u64 b) {
    asm("fma.rn.f32x2 %0, %1, %2, %3;" : "=l"(d) : "l"(a), "l"(b), "l"(d));
}
__device__ __forceinline__ u64 add2(u64 a, u64 b) {
    u64 r; asm("add.rn.f32x2 %0, %1, %2;" : "=l"(r) : "l"(a), "l"(b)); return r;
}
__device__ __forceinline__ void unpack2(u64 v, float &lo, float &hi) {
    asm("mov.b64 {%0,%1}, %2;" : "=f"(lo), "=f"(hi) : "l"(v));
}
__device__ __forceinline__ void lds_v2u64(u64 &a, u64 &b, const void* p) {
    unsigned sa = (unsigned)__cvta_generic_to_shared(p);
    asm("ld.shared.v2.u64 {%0, %1}, [%2];" : "=l"(a), "=l"(b) : "r"(sa));
}
__device__ __forceinline__ void red4(float4* p, float4 v) {
    asm volatile("red.global.add.v4.f32 [%0], {%1,%2,%3,%4};"
                 :: "l"(p), "f"(v.x), "f"(v.y), "f"(v.z), "f"(v.w) : "memory");
}

// ================= K0: zero everything ==========================================
__global__ void k_zero() {
    int t = blockIdx.x * 256 + threadIdx.x;
    if (t < 600000) ((float4*)g_agg48)[t] = make_float4(0.f, 0.f, 0.f, 0.f);
    if (t < 128) { ((float*)g_s1)[t] = 0.f; ((float*)g_s2)[t] = 0.f; }
}

// ================= K1: edge scatter (4 threads/edge, 3 red.v4 each) ==============
__global__ void __launch_bounds__(256) k_scatter(const int* __restrict__ ei,
                                                 const float* __restrict__ x,
                                                 const float* __restrict__ c) {
    unsigned tid = blockIdx.x * 256u + threadIdx.x;
    unsigned e = tid >> 2;
    if (e >= N_EDGES) return;
    unsigned q = tid & 3;
    int src = __ldg(ei + e);
    int dst = __ldg(ei + N_EDGES + e);
    const float4* x4 = reinterpret_cast<const float4*>(x);
    const float4* c4 = reinterpret_cast<const float4*>(c);
    float4 vx = __ldg(&x4[src * 4 + q]);
    float4 v0 = __ldg(&c4[src * 8 + q]);
    float4 v1 = __ldg(&c4[src * 8 + 4 + q]);
    float4* d = reinterpret_cast<float4*>(g_agg48) + dst * 12;
    red4(d + q, vx);
    red4(d + 4 + q, v0);
    red4(d + 8 + q, v1);
}

// ================= K2: layer-1 + BN moment stats + z-cache store =================
__global__ void __launch_bounds__(256) k_stats(const float* __restrict__ x,
                                               const float* __restrict__ c,
                                               const float* __restrict__ W1s,
                                               const float* __restrict__ b1s,
                                               const float* __restrict__ W1a,
                                               const float* __restrict__ b1a,
                                               const float* __restrict__ eps_s_p,
                                               const float* __restrict__ eps_a_p) {
    __shared__ float4 w1qs[24][16], w1qa[24][16];
    __shared__ float msx[8][2][16], msc[8][2][4][8];
    __shared__ float max_[8][2][16], mac[8][2][8];
    __shared__ float red[8][16][16];
    int tid = threadIdx.x;
    for (int i = tid; i < 24 * 16; i += 256) {
        int j = i >> 4, l = i & 15;
        w1qs[j][l] = *reinterpret_cast<const float4*>(&W1s[j * 64 + 4 * l]);
        w1qa[j][l] = *reinterpret_cast<const float4*>(&W1a[j * 64 + 4 * l]);
    }
    float es = 1.f + __ldg(eps_s_p);
    float ea = 1.f + __ldg(eps_a_p);
    __syncthreads();
    int w = tid >> 5, lane = tid & 31, l16 = lane & 15, nd = lane >> 4;
    float4 bs4 = __ldg(reinterpret_cast<const float4*>(b1s) + l16);
    float4 ba4 = __ldg(reinterpret_cast<const float4*>(b1a) + l16);
    u64 bs0 = pack2(bs4.x, bs4.y), bs1 = pack2(bs4.z, bs4.w);
    u64 ba0 = pack2(ba4.x, ba4.y), ba1 = pack2(ba4.z, ba4.w);
    float ss[4] = {0,0,0,0}, sq[4] = {0,0,0,0}, as_[4] = {0,0,0,0}, aq[4] = {0,0,0,0};
    for (int p = blockIdx.x * 8 + w; p < 25000; p += gridDim.x * 8) {
        int nA = 2 * p;
        __syncwarp();
#pragma unroll
        for (int it = 0; it < 4; it++) {
            int idx = lane + 32 * it;
            int node = idx >> 6, r = idx & 63, n = nA + node;
            if (r < 16) msx[w][node][r] = es * x[n * 16 + r] + g_agg48[n * 48 + r];
            else if (r < 48) {
                int s = (r - 16) >> 3, j = (r - 16) & 7;
                msc[w][node][s][j] = es * c[n * 32 + s * 8 + j] + g_agg48[n * 48 + 16 + s * 8 + j];
            } else {
                int j = r - 48;
                max_[w][node][j] = ea * x[n * 16 + j] + g_agg48[n * 48 + j];
            }
        }
        __syncwarp();
        if (lane < 16) {
            int node = lane >> 3, j = lane & 7, n = nA + node;
            float csum = c[n*32 + j] + c[n*32 + 8 + j] + c[n*32 + 16 + j] + c[n*32 + 24 + j];
            float msum = msc[w][node][0][j] + msc[w][node][1][j]
                       + msc[w][node][2][j] + msc[w][node][3][j];
            mac[w][node][j] = 0.25f * (msum + (ea - es) * csum);
        }
        __syncwarp();
        u64 zc0 = bs0, zc1 = bs1, za0 = ba0, za1 = ba1;
#pragma unroll
        for (int j = 0; j < 16; j++) {
            u64 w0, w1; lds_v2u64(w0, w1, &w1qs[j][l16]);
            u64 h = dup2(msx[w][nd][j]);
            fma2(zc0, w0, h); fma2(zc1, w1, h);
            u64 a0, a1; lds_v2u64(a0, a1, &w1qa[j][l16]);
            u64 ha = dup2(max_[w][nd][j]);
            fma2(za0, a0, ha); fma2(za1, a1, ha);
        }
        u64 zs0[4], zs1[4];
#pragma unroll
        for (int s = 0; s < 4; s++) { zs0[s] = zc0; zs1[s] = zc1; }
#pragma unroll
        for (int j = 0; j < 8; j++) {
            u64 w0, w1; lds_v2u64(w0, w1, &w1qs[16 + j][l16]);
#pragma unroll
            for (int s = 0; s < 4; s++) {
                u64 h = dup2(msc[w][nd][s][j]);
                fma2(zs0[s], w0, h); fma2(zs1[s], w1, h);
            }
            u64 a0, a1; lds_v2u64(a0, a1, &w1qa[16 + j][l16]);
            u64 ha = dup2(mac[w][nd][j]);
            fma2(za0, a0, ha); fma2(za1, a1, ha);
        }
        int n = nA + nd;
#pragma unroll
        for (int s = 0; s < 4; s++) {
            float z0, z1, z2, z3;
            unpack2(zs0[s], z0, z1); unpack2(zs1[s], z2, z3);
            *reinterpret_cast<float4*>(&g_z[n * 320 + s * 64 + 4 * l16]) =
                make_float4(z0, z1, z2, z3);
            ss[0] += z0; ss[1] += z1; ss[2] += z2; ss[3] += z3;
            sq[0] += z0*z0; sq[1] += z1*z1; sq[2] += z2*z2; sq[3] += z3*z3;
        }
        {
            float z0, z1, z2, z3;
            unpack2(za0, z0, z1); unpack2(za1, z2, z3);
            *reinterpret_cast<float4*>(&g_z[n * 320 + 4 * 64 + 4 * l16]) =
                make_float4(z0, z1, z2, z3);
            as_[0] += z0; as_[1] += z1; as_[2] += z2; as_[3] += z3;
            aq[0] += z0*z0; aq[1] += z1*z1; aq[2] += z2*z2; aq[3] += z3*z3;
        }
    }
#pragma unroll
    for (int i = 0; i < 4; i++) {
        ss[i]  += __shfl_xor_sync(0xffffffffu, ss[i], 16);
        sq[i]  += __shfl_xor_sync(0xffffffffu, sq[i], 16);
        as_[i] += __shfl_xor_sync(0xffffffffu, as_[i], 16);
        aq[i]  += __shfl_xor_sync(0xffffffffu, aq[i], 16);
    }
    if (lane < 16) {
#pragma unroll
        for (int i = 0; i < 4; i++) {
            red[w][l16][i]      = ss[i];
            red[w][l16][4 + i]  = sq[i];
            red[w][l16][8 + i]  = as_[i];
            red[w][l16][12 + i] = aq[i];
        }
    }
    __syncthreads();
    {
        int l = tid >> 4, v = tid & 15;
        float acc = 0.f;
#pragma unroll
        for (int ww = 0; ww < 8; ww++) acc += red[ww][l][v];
        int col = 4 * l + (v & 3);
        if (v < 4)       atomicAdd(&g_s1[0][col], acc);
        else if (v < 8)  atomicAdd(&g_s2[0][col], acc);
        else if (v < 12) atomicAdd(&g_s1[1][col], acc);
        else             atomicAdd(&g_s2[1][col], acc);
    }
}

// ================= K3: z-cached BN+relu staging + layer-2 + DSS -> out ===========
// cons rows: 0/1 b2s lo/hi, 2/3 b2a lo/hi
__global__ void __launch_bounds__(256, 2) k_main(const float* __restrict__ W2s,
                                                 const float* __restrict__ b2s,
                                                 const float* __restrict__ W2a,
                                                 const float* __restrict__ b2a,
                                                 const float* __restrict__ g1s,
                                                 const float* __restrict__ be1s,
                                                 const float* __restrict__ g1a,
                                                 const float* __restrict__ be1a,
                                                 float* __restrict__ out) {
    __shared__ float4 w2qs[64][16], w2qa[64][16];
    __shared__ u64 cons[4][16];
    __shared__ __align__(16) float alf[2][64], bet[2][64];  // [0]=shared, [1]=agg
    __shared__ __align__(16) float hs[8][4][5][64];
    int tid = threadIdx.x;
    for (int i = tid; i < 64 * 16; i += 256) {
        int k = i >> 4, l = i & 15;
        w2qs[k][l] = *reinterpret_cast<const float4*>(&W2s[k * 64 + 4 * l]);
        w2qa[k][l] = *reinterpret_cast<const float4*>(&W2a[k * 64 + 4 * l]);
    }
    if (tid < 16) {
        float4 v;
        v = __ldg(reinterpret_cast<const float4*>(b2s) + tid);
        cons[0][tid] = pack2(v.x, v.y); cons[1][tid] = pack2(v.z, v.w);
        v = __ldg(reinterpret_cast<const float4*>(b2a) + tid);
        cons[2][tid] = pack2(v.x, v.y); cons[3][tid] = pack2(v.z, v.w);
        {
            float4 s1v = *reinterpret_cast<const float4*>(&g_s1[0][4 * tid]);
            float4 s2v = *reinterpret_cast<const float4*>(&g_s2[0][4 * tid]);
            float4 g1v = __ldg(reinterpret_cast<const float4*>(g1s) + tid);
            float4 bev = __ldg(reinterpret_cast<const float4*>(be1s) + tid);
            const float invR = 1.f / 200000.f;
            float m0 = s1v.x*invR, m1 = s1v.y*invR, m2 = s1v.z*invR, m3 = s1v.w*invR;
            float a0 = g1v.x * rsqrtf(s2v.x*invR - m0*m0 + 1e-5f);
            float a1 = g1v.y * rsqrtf(s2v.y*invR - m1*m1 + 1e-5f);
            float a2 = g1v.z * rsqrtf(s2v.z*invR - m2*m2 + 1e-5f);
            float a3 = g1v.w * rsqrtf(s2v.w*invR - m3*m3 + 1e-5f);
            *reinterpret_cast<float4*>(&alf[0][4 * tid]) = make_float4(a0, a1, a2, a3);
            *reinterpret_cast<float4*>(&bet[0][4 * tid]) = make_float4(
                bev.x - a0*m0, bev.y - a1*m1, bev.z - a2*m2, bev.w - a3*m3);
        }
        {
            float4 s1v = *reinterpret_cast<const float4*>(&g_s1[1][4 * tid]);
            float4 s2v = *reinterpret_cast<const float4*>(&g_s2[1][4 * tid]);
            float4 g1v = __ldg(reinterpret_cast<const float4*>(g1a) + tid);
            float4 bev = __ldg(reinterpret_cast<const float4*>(be1a) + tid);
            const float invR = 1.f / 50000.f;
            float m0 = s1v.x*invR, m1 = s1v.y*invR, m2 = s1v.z*invR, m3 = s1v.w*invR;
            float a0 = g1v.x * rsqrtf(s2v.x*invR - m0*m0 + 1e-5f);
            float a1 = g1v.y * rsqrtf(s2v.y*invR - m1*m1 + 1e-5f);
            float a2 = g1v.z * rsqrtf(s2v.z*invR - m2*m2 + 1e-5f);
            float a3 = g1v.w * rsqrtf(s2v.w*invR - m3*m3 + 1e-5f);
            *reinterpret_cast<float4*>(&alf[1][4 * tid]) = make_float4(a0, a1, a2, a3);
            *reinterpret_cast<float4*>(&bet[1][4 * tid]) = make_float4(
                bev.x - a0*m0, bev.y - a1*m1, bev.z - a2*m2, bev.w - a3*m3);
        }
    }
    int w = tid >> 5, lane = tid & 31, l16 = lane & 15, nd = lane >> 4;
    __syncthreads();
    for (int p = blockIdx.x * 8 + w; p < 12500; p += gridDim.x * 8) {
        int nA = 4 * p;
        __syncwarp();
        // ---- stage z from L2, apply BN + relu -> hs (4 nodes x 5 rows x 64) ----
#pragma unroll
        for (int it = 0; it < 10; it++) {
            int idx = lane + 32 * it;             // 0..319 float4 units
            int node = idx / 80;
            int rem = idx - node * 80;
            int row = rem >> 4, c4 = rem & 15;
            int path = (row == 4) ? 1 : 0;
            float4 z = *reinterpret_cast<const float4*>(
                &g_z[(nA + node) * 320 + row * 64 + 4 * c4]);
            float4 al = *reinterpret_cast<const float4*>(&alf[path][4 * c4]);
            float4 be = *reinterpret_cast<const float4*>(&bet[path][4 * c4]);
            *reinterpret_cast<float4*>(&hs[w][node][row][4 * c4]) = make_float4(
                fmaxf(al.x * z.x + be.x, 0.f), fmaxf(al.y * z.y + be.y, 0.f),
                fmaxf(al.z * z.z + be.z, 0.f), fmaxf(al.w * z.w + be.w, 0.f));
        }
        __syncwarp();
        // ---- layer 2: 2 nodes x 5 rows per half-warp (anchor loop) ----
        u64 o[2][5][2];
#pragma unroll
        for (int i = 0; i < 2; i++) {
#pragma unroll
            for (int s = 0; s < 4; s++) { o[i][s][0] = cons[0][l16]; o[i][s][1] = cons[1][l16]; }
            o[i][4][0] = cons[2][l16]; o[i][4][1] = cons[3][l16];
        }
#pragma unroll
        for (int k0 = 0; k0 < 64; k0 += 2) {
            float2 hv[2][5];
#pragma unroll
            for (int i = 0; i < 2; i++)
#pragma unroll
                for (int s = 0; s < 5; s++)
                    hv[i][s] = *reinterpret_cast<const float2*>(&hs[w][2 * nd + i][s][k0]);
#pragma unroll
            for (int kk = 0; kk < 2; kk++) {
                u64 w0, w1; lds_v2u64(w0, w1, &w2qs[k0 + kk][l16]);
                u64 a0, a1; lds_v2u64(a0, a1, &w2qa[k0 + kk][l16]);
#pragma unroll
                for (int i = 0; i < 2; i++) {
#pragma unroll
                    for (int s = 0; s < 4; s++) {
                        u64 h = dup2(kk ? hv[i][s].y : hv[i][s].x);
                        fma2(o[i][s][0], w0, h); fma2(o[i][s][1], w1, h);
                    }
                    u64 h4 = dup2(kk ? hv[i][4].y : hv[i][4].x);
                    fma2(o[i][4][0], a0, h4); fma2(o[i][4][1], a1, h4);
                }
            }
        }
        // ---- DSS combine + store ----
#pragma unroll
        for (int i = 0; i < 2; i++) {
            int n = nA + 2 * nd + i;
#pragma unroll
            for (int s = 0; s < 4; s++) {
                u64 t0 = add2(o[i][s][0], o[i][4][0]);
                u64 t1 = add2(o[i][s][1], o[i][4][1]);
                float r0, r1, r2, r3;
                unpack2(t0, r0, r1); unpack2(t1, r2, r3);
                *reinterpret_cast<float4*>(&out[n * 256 + s * 64 + 4 * l16]) =
                    make_float4(r0, r1, r2, r3);
            }
        }
    }
}

// ================= launch ========================================================
extern "C" void kernel_launch(void* const* d_in, const int* in_sizes, int n_in,
                              void* d_out, int out_size) {
    const float* x     = (const float*)d_in[0];
    const float* c     = (const float*)d_in[1];
    const int*   ei    = (const int*)  d_in[2];
    const float* eps_s = (const float*)d_in[3];
    const float* W1s   = (const float*)d_in[4];
    const float* b1s   = (const float*)d_in[5];
    const float* g1s   = (const float*)d_in[6];
    const float* be1s  = (const float*)d_in[7];
    const float* W2s   = (const float*)d_in[8];
    const float* b2s   = (const float*)d_in[9];
    const float* eps_a = (const float*)d_in[10];
    const float* W1a   = (const float*)d_in[11];
    const float* b1a   = (const float*)d_in[12];
    const float* g1a   = (const float*)d_in[13];
    const float* be1a  = (const float*)d_in[14];
    const float* W2a   = (const float*)d_in[15];
    const float* b2a   = (const float*)d_in[16];
    float* out = (float*)d_out;

    k_zero   <<<2344, 256>>>();
    k_scatter<<<(N_EDGES * 4 + 255) / 256, 256>>>(ei, x, c);
    k_stats  <<<296, 256>>>(x, c, W1s, b1s, W1a, b1a, eps_s, eps_a);
    k_main   <<<296, 256>>>(W2s, b2s, W2a, b2a, g1s, be1s, g1a, be1a, out);
}